// round 5
// baseline (speedup 1.0000x reference)
#include <cuda_runtime.h>
#include <math.h>

#define NTOK   8192
#define DMODEL 512
#define HID    2048
#define NEXP   8
#define CAP    16384
#define PD     588
#define PDP    592   // PD padded to multiple of 16 for guard-free K loop

// ------------------------- scratch (device globals; no allocs) -------------
__device__ float g_patches[(size_t)NTOK * PDP];
__device__ float g_e   [(size_t)NTOK * DMODEL];
__device__ float g_ln  [(size_t)NTOK * DMODEL];
__device__ float g_q   [(size_t)NTOK * DMODEL];
__device__ float g_k   [(size_t)NTOK * DMODEL];
__device__ float g_v   [(size_t)NTOK * DMODEL];
__device__ float g_attn[(size_t)65536 * 256];     // [B*H, 256, 256]
__device__ float g_ctx [(size_t)NTOK * DMODEL];
__device__ float g_e2  [(size_t)NTOK * DMODEL];
__device__ float g_xm  [(size_t)NTOK * DMODEL];
__device__ float g_H   [(size_t)CAP * HID];
__device__ float g_Y   [(size_t)CAP * DMODEL];
__device__ float g_o1  [(size_t)NTOK * DMODEL];
__device__ float g_o2  [(size_t)NTOK * DMODEL];
__device__ int   g_lists[NEXP * CAP];
__device__ float g_gates[CAP];
__device__ int   g_counts[16];   // [layer][8]
__device__ float g_imp[16];

__device__ __forceinline__ float gelu_f(float v) {
    return 0.5f * v * (1.0f + erff(v * 0.7071067811865476f));
}

// ------------------------- f32x2 packed-FMA helpers ------------------------
__device__ __forceinline__ void ffma2(unsigned long long& d, unsigned long long a,
                                      unsigned long long b) {
    asm("fma.rn.f32x2 %0, %1, %2, %0;" : "+l"(d) : "l"(a), "l"(b));
}
__device__ __forceinline__ unsigned long long dup2(float x) {
    unsigned long long r;
    asm("mov.b64 %0, {%1, %1};" : "=l"(r) : "f"(x));
    return r;
}
__device__ __forceinline__ float2 unpk(unsigned long long v) {
    float2 r;
    asm("mov.b64 {%0, %1}, %2;" : "=f"(r.x), "=f"(r.y) : "l"(v));
    return r;
}

// ------------------------- small kernels -----------------------------------
__global__ void zero_k() {
    int t = threadIdx.x;
    if (t < 16) { g_counts[t] = 0; g_imp[t] = 0.f; }
}

__global__ void patchify_k(const float* __restrict__ x) {
    long t = (long)blockIdx.x * 256 + threadIdx.x;
    if (t >= (long)NTOK * PDP) return;
    int p = (int)(t % PDP);
    long token = t / PDP;
    if (p >= PD) { g_patches[t] = 0.f; return; }
    int b = (int)(token >> 8), s = (int)(token & 255);
    int hh = s >> 4, ww = s & 15;
    int c = p % 3; int pp = p / 3;
    int p1 = pp / 14, p2 = pp % 14;
    g_patches[t] = x[(((long)b * 3 + c) * 224 + hh * 14 + p1) * 224 + ww * 14 + p2];
}

// ------------------------- packed-FMA 128x128 GEMM -------------------------
// C[M,N] = A[M,K] @ B[K,N] + bias.  M multiple of 128 (or gather w/ guards),
// N multiple of 128, K multiple of 16.  256 threads, 16x4 microtile.
// EPI 0: dense, +bias
// EPI 1: dense, +bias + extra[m*N+n]           (residual)
// EPI 2: dense, +bias + extra[(m&255)*N+n]     (positional)
// EPI 3: gather (ent>>1 rows of A), gelu(.+bias)     -> C[ent*ldc+n]
// EPI 4: gather (ent   rows of A), (.+bias)*gate[ent]-> C[ent*ldc+n]
template<int EPI>
__global__ __launch_bounds__(256, 2)
void gemm_f2(const float* __restrict__ A, int lda,
             const float* __restrict__ B, int ldb,
             float* __restrict__ C, int ldc,
             int M, int N, int K,
             const float* __restrict__ bias,
             const float* __restrict__ extra,
             int layer)
{
    __shared__ unsigned long long As2[16][64];   // [k][m-pair]
    __shared__ float Bs[16][128];
    __shared__ int rows_s[128];

    int tid = threadIdx.x;
    int tx = tid & 31, ty = tid >> 5;            // ty 0..7, tx 0..31
    int m0 = blockIdx.x * 128, n0 = blockIdx.y * 128;
    int e = blockIdx.z;

    if (EPI >= 3) {
        int cnt = g_counts[layer * 8 + e];
        if (m0 >= cnt) return;
        B    += (size_t)e * K * N;
        bias += (size_t)e * N;
        if (tid < 128) rows_s[tid] = (m0 + tid < cnt) ? g_lists[e * CAP + m0 + tid] : -1;
        __syncthreads();
    }

    // A loader mapping: each thread owns row (m0+am), k-halves kg*8..kg*8+7
    int am = tid & 127, kg = tid >> 7;
    const float* arow;
    bool avalid = true;
    if (EPI == 3) {
        int ent = rows_s[am]; avalid = (ent >= 0);
        arow = A + (size_t)(ent >> 1) * lda;
    } else if (EPI == 4) {
        int ent = rows_s[am]; avalid = (ent >= 0);
        arow = A + (size_t)ent * lda;
    } else {
        arow = A + (size_t)(m0 + am) * lda;
    }
    // B loader mapping
    int br = tid >> 5;                  // 0..7 (and +8)
    int bc = (tid & 31) * 4;

    float* Asf = (float*)As2;           // [k][m] float view, row stride 128

    unsigned long long acc[8][4];
    #pragma unroll
    for (int p = 0; p < 8; p++)
        #pragma unroll
        for (int j = 0; j < 4; j++) acc[p][j] = 0ull;

    for (int kk = 0; kk < K; kk += 16) {
        float4 a0, a1;
        if (avalid) {
            a0 = *(const float4*)&arow[kk + kg * 8];
            a1 = *(const float4*)&arow[kk + kg * 8 + 4];
        } else {
            a0 = make_float4(0.f, 0.f, 0.f, 0.f);
            a1 = a0;
        }
        float4 b0 = *(const float4*)&B[(size_t)(kk + br) * ldb + n0 + bc];
        float4 b1 = *(const float4*)&B[(size_t)(kk + br + 8) * ldb + n0 + bc];
        __syncthreads();   // previous iteration's compute done
        Asf[(kg * 8 + 0) * 128 + am] = a0.x;
        Asf[(kg * 8 + 1) * 128 + am] = a0.y;
        Asf[(kg * 8 + 2) * 128 + am] = a0.z;
        Asf[(kg * 8 + 3) * 128 + am] = a0.w;
        Asf[(kg * 8 + 4) * 128 + am] = a1.x;
        Asf[(kg * 8 + 5) * 128 + am] = a1.y;
        Asf[(kg * 8 + 6) * 128 + am] = a1.z;
        Asf[(kg * 8 + 7) * 128 + am] = a1.w;
        Bs[br][bc + 0] = b0.x; Bs[br][bc + 1] = b0.y;
        Bs[br][bc + 2] = b0.z; Bs[br][bc + 3] = b0.w;
        Bs[br + 8][bc + 0] = b1.x; Bs[br + 8][bc + 1] = b1.y;
        Bs[br + 8][bc + 2] = b1.z; Bs[br + 8][bc + 3] = b1.w;
        __syncthreads();
        #pragma unroll
        for (int k = 0; k < 16; k++) {
            const ulonglong2* ar = (const ulonglong2*)&As2[k][ty * 8];
            ulonglong2 q0 = ar[0], q1 = ar[1], q2 = ar[2], q3 = ar[3];
            unsigned long long bd0 = dup2(Bs[k][tx]);
            unsigned long long bd1 = dup2(Bs[k][tx + 32]);
            unsigned long long bd2 = dup2(Bs[k][tx + 64]);
            unsigned long long bd3 = dup2(Bs[k][tx + 96]);
            unsigned long long av[8] = {q0.x, q0.y, q1.x, q1.y, q2.x, q2.y, q3.x, q3.y};
            #pragma unroll
            for (int p = 0; p < 8; p++) {
                ffma2(acc[p][0], av[p], bd0);
                ffma2(acc[p][1], av[p], bd1);
                ffma2(acc[p][2], av[p], bd2);
                ffma2(acc[p][3], av[p], bd3);
            }
        }
    }

    // epilogue: thread covers rows m0+ty*16+2p(+1), cols n0+tx+32j
    float bi[4];
    #pragma unroll
    for (int j = 0; j < 4; j++) bi[j] = bias[n0 + tx + 32 * j];

    #pragma unroll
    for (int p = 0; p < 8; p++) {
        int m = ty * 16 + 2 * p;
        float2 c0 = unpk(acc[p][0]);
        float2 c1 = unpk(acc[p][1]);
        float2 c2 = unpk(acc[p][2]);
        float2 c3 = unpk(acc[p][3]);
        float r0[4] = {c0.x + bi[0], c1.x + bi[1], c2.x + bi[2], c3.x + bi[3]};
        float r1[4] = {c0.y + bi[0], c1.y + bi[1], c2.y + bi[2], c3.y + bi[3]};
        if (EPI <= 2) {
            size_t gm0 = (size_t)(m0 + m);
            #pragma unroll
            for (int rr = 0; rr < 2; rr++) {
                float* r = rr ? r1 : r0;
                size_t gm = gm0 + rr;
                #pragma unroll
                for (int j = 0; j < 4; j++) {
                    int n = n0 + tx + 32 * j;
                    float v = r[j];
                    if (EPI == 1) v += extra[gm * N + n];
                    if (EPI == 2) v += extra[(size_t)((int)gm & 255) * N + n];
                    C[gm * ldc + n] = v;
                }
            }
        } else {
            #pragma unroll
            for (int rr = 0; rr < 2; rr++) {
                int ent = rows_s[m + rr];
                if (ent < 0) continue;
                float* r = rr ? r1 : r0;
                if (EPI == 3) {
                    #pragma unroll
                    for (int j = 0; j < 4; j++)
                        C[(size_t)ent * ldc + n0 + tx + 32 * j] = gelu_f(r[j]);
                } else {
                    float gate = g_gates[ent];
                    #pragma unroll
                    for (int j = 0; j < 4; j++)
                        C[(size_t)ent * ldc + n0 + tx + 32 * j] = r[j] * gate;
                }
            }
        }
    }
}

// ------------------------- small 64x64 GEMM (cls head only) ----------------
template<int EPI>
__global__ __launch_bounds__(256)
void gemm_nn(const float* __restrict__ A, int lda,
             const float* __restrict__ B, int ldb,
             float* __restrict__ C, int ldc,
             int M, int N, int K,
             const float* __restrict__ bias,
             const float* __restrict__ extra)
{
    __shared__ float As[16][65];
    __shared__ float Bs[16][65];
    int tid = threadIdx.x;
    int tx = tid & 15, ty = tid >> 4;
    int m0 = blockIdx.x * 64, n0 = blockIdx.y * 64;
    float acc[4][4] = {};
    for (int kk = 0; kk < K; kk += 16) {
        #pragma unroll
        for (int i = 0; i < 4; i++) {
            int idx = tid + i * 256;
            int r = idx >> 4, c = idx & 15;
            int m = m0 + r, k = kk + c;
            As[c][r] = (m < M && k < K) ? A[(long)m * lda + k] : 0.f;
        }
        #pragma unroll
        for (int i = 0; i < 4; i++) {
            int idx = tid + i * 256;
            int r = idx >> 6, c = idx & 63;
            int k = kk + r, n = n0 + c;
            Bs[r][c] = (k < K && n < N) ? B[(long)k * ldb + n] : 0.f;
        }
        __syncthreads();
        #pragma unroll
        for (int k = 0; k < 16; k++) {
            float a[4], b[4];
            #pragma unroll
            for (int i = 0; i < 4; i++) a[i] = As[k][ty * 4 + i];
            #pragma unroll
            for (int j = 0; j < 4; j++) b[j] = Bs[k][tx * 4 + j];
            #pragma unroll
            for (int i = 0; i < 4; i++)
                #pragma unroll
                for (int j = 0; j < 4; j++)
                    acc[i][j] = fmaf(a[i], b[j], acc[i][j]);
        }
        __syncthreads();
    }
    #pragma unroll
    for (int i = 0; i < 4; i++) {
        int m = m0 + ty * 4 + i;
        if (m >= M) continue;
        #pragma unroll
        for (int j = 0; j < 4; j++) {
            int n = n0 + tx * 4 + j;
            if (n >= N) continue;
            float v = acc[i][j] + (bias ? bias[n] : 0.f);
            C[(long)m * ldc + n] = v;
        }
    }
}

// ------------------------- layernorm ---------------------------------------
__global__ __launch_bounds__(256)
void layernorm_k(const float* __restrict__ X, const float* __restrict__ g,
                 const float* __restrict__ bb, float* __restrict__ Y)
{
    __shared__ float red[8];
    __shared__ float mean_s, inv_s;
    long row = blockIdx.x;
    const float* x = X + row * DMODEL;
    int t = threadIdx.x;
    float v0 = x[t], v1 = x[t + 256];
    float s = v0 + v1;
    #pragma unroll
    for (int o = 16; o; o >>= 1) s += __shfl_down_sync(0xffffffffu, s, o);
    if ((t & 31) == 0) red[t >> 5] = s;
    __syncthreads();
    if (t == 0) {
        float q = 0.f;
        #pragma unroll
        for (int w = 0; w < 8; w++) q += red[w];
        mean_s = q * (1.f / DMODEL);
    }
    __syncthreads();
    float mean = mean_s;
    float d0 = v0 - mean, d1 = v1 - mean;
    float s2 = d0 * d0 + d1 * d1;
    #pragma unroll
    for (int o = 16; o; o >>= 1) s2 += __shfl_down_sync(0xffffffffu, s2, o);
    if ((t & 31) == 0) red[t >> 5] = s2;
    __syncthreads();
    if (t == 0) {
        float q = 0.f;
        #pragma unroll
        for (int w = 0; w < 8; w++) q += red[w];
        inv_s = rsqrtf(q * (1.f / DMODEL) + 1e-5f);
    }
    __syncthreads();
    float inv = inv_s;
    Y[row * DMODEL + t]       = d0 * inv * g[t]       + bb[t];
    Y[row * DMODEL + t + 256] = d1 * inv * g[t + 256] + bb[t + 256];
}

// ------------------------- attention ---------------------------------------
__global__ __launch_bounds__(256)
void attn_scores_k(const float* __restrict__ Q, const float* __restrict__ Kt)
{
    int bh = blockIdx.z; int b = bh >> 3, h = bh & 7;
    const float* A = Q  + (long)b * 256 * 512 + h * 64;
    const float* B = Kt + (long)b * 256 * 512 + h * 64;
    float* C = g_attn + (long)bh * 65536;
    int m0 = blockIdx.x * 64, n0 = blockIdx.y * 64;
    __shared__ float As[16][65], Bs[16][65];
    int tid = threadIdx.x, tx = tid & 15, ty = tid >> 4;
    float acc[4][4] = {};
    for (int kk = 0; kk < 64; kk += 16) {
        #pragma unroll
        for (int i = 0; i < 4; i++) {
            int idx = tid + i * 256;
            int r = idx >> 4, c = idx & 15;
            As[c][r] = A[(long)(m0 + r) * 512 + kk + c];
            Bs[c][r] = B[(long)(n0 + r) * 512 + kk + c];
        }
        __syncthreads();
        #pragma unroll
        for (int k = 0; k < 16; k++) {
            float a[4], bv[4];
            #pragma unroll
            for (int i = 0; i < 4; i++) a[i]  = As[k][ty * 4 + i];
            #pragma unroll
            for (int j = 0; j < 4; j++) bv[j] = Bs[k][tx * 4 + j];
            #pragma unroll
            for (int i = 0; i < 4; i++)
                #pragma unroll
                for (int j = 0; j < 4; j++)
                    acc[i][j] = fmaf(a[i], bv[j], acc[i][j]);
        }
        __syncthreads();
    }
    #pragma unroll
    for (int i = 0; i < 4; i++)
        #pragma unroll
        for (int j = 0; j < 4; j++)
            C[(long)(m0 + ty * 4 + i) * 256 + n0 + tx * 4 + j] = acc[i][j] * 0.125f;
}

__global__ __launch_bounds__(256)
void softmax256_k(float* __restrict__ S)
{
    __shared__ float red[8];
    __shared__ float mx_s, sum_s;
    long row = blockIdx.x;
    float* p = S + row * 256;
    int t = threadIdx.x;
    float v = p[t];
    float m = v;
    #pragma unroll
    for (int o = 16; o; o >>= 1) m = fmaxf(m, __shfl_xor_sync(0xffffffffu, m, o));
    if ((t & 31) == 0) red[t >> 5] = m;
    __syncthreads();
    if (t == 0) {
        float q = red[0];
        #pragma unroll
        for (int w = 1; w < 8; w++) q = fmaxf(q, red[w]);
        mx_s = q;
    }
    __syncthreads();
    float ex = expf(v - mx_s);
    float s = ex;
    #pragma unroll
    for (int o = 16; o; o >>= 1) s += __shfl_xor_sync(0xffffffffu, s, o);
    if ((t & 31) == 0) red[t >> 5] = s;
    __syncthreads();
    if (t == 0) {
        float q = 0.f;
        #pragma unroll
        for (int w = 0; w < 8; w++) q += red[w];
        sum_s = q;
    }
    __syncthreads();
    p[t] = ex / sum_s;
}

__global__ __launch_bounds__(256)
void attn_ctx_k(const float* __restrict__ V)
{
    int bh = blockIdx.y; int b = bh >> 3, h = bh & 7;
    const float* A = g_attn + (long)bh * 65536;
    int m0 = blockIdx.x * 64;
    __shared__ float As[16][65], Bs[16][65];
    int tid = threadIdx.x, tx = tid & 15, ty = tid >> 4;
    float acc[4][4] = {};
    for (int kk = 0; kk < 256; kk += 16) {
        #pragma unroll
        for (int i = 0; i < 4; i++) {
            int idx = tid + i * 256;
            int r = idx >> 4, c = idx & 15;
            As[c][r] = A[(long)(m0 + r) * 256 + kk + c];
        }
        #pragma unroll
        for (int i = 0; i < 4; i++) {
            int idx = tid + i * 256;
            int r = idx >> 6, c = idx & 63;
            Bs[r][c] = V[((long)b * 256 + kk + r) * 512 + h * 64 + c];
        }
        __syncthreads();
        #pragma unroll
        for (int k = 0; k < 16; k++) {
            float a[4], bv[4];
            #pragma unroll
            for (int i = 0; i < 4; i++) a[i]  = As[k][ty * 4 + i];
            #pragma unroll
            for (int j = 0; j < 4; j++) bv[j] = Bs[k][tx * 4 + j];
            #pragma unroll
            for (int i = 0; i < 4; i++)
                #pragma unroll
                for (int j = 0; j < 4; j++)
                    acc[i][j] = fmaf(a[i], bv[j], acc[i][j]);
        }
        __syncthreads();
    }
    #pragma unroll
    for (int i = 0; i < 4; i++)
        #pragma unroll
        for (int j = 0; j < 4; j++)
            g_ctx[((long)b * 256 + m0 + ty * 4 + i) * 512 + h * 64 + tx * 4 + j] = acc[i][j];
}

__global__ __launch_bounds__(256)
void attn_mean_k(float* __restrict__ out)
{
    __shared__ float red[8];
    __shared__ float mx_s, sum_s;
    int row = blockIdx.x;           // b*256 + q
    int b = row >> 8, q = row & 255;
    int t = threadIdx.x;
    float s = 0.f;
    #pragma unroll
    for (int h = 0; h < 8; h++)
        s += g_attn[(((long)(b * 8 + h)) * 256 + q) * 256 + t];
    s *= 0.125f;
    float m = s;
    #pragma unroll
    for (int o = 16; o; o >>= 1) m = fmaxf(m, __shfl_xor_sync(0xffffffffu, m, o));
    if ((t & 31) == 0) red[t >> 5] = m;
    __syncthreads();
    if (t == 0) {
        float q2 = red[0];
        #pragma unroll
        for (int w = 1; w < 8; w++) q2 = fmaxf(q2, red[w]);
        mx_s = q2;
    }
    __syncthreads();
    float ex = expf(s - mx_s);
    float ss = ex;
    #pragma unroll
    for (int o = 16; o; o >>= 1) ss += __shfl_xor_sync(0xffffffffu, ss, o);
    if ((t & 31) == 0) red[t >> 5] = ss;
    __syncthreads();
    if (t == 0) {
        float q2 = 0.f;
        #pragma unroll
        for (int w = 0; w < 8; w++) q2 += red[w];
        sum_s = q2;
    }
    __syncthreads();
    out[(long)row * 256 + t] = ex / sum_s;
}

// ------------------------- MoE router --------------------------------------
__global__ __launch_bounds__(256)
void router_k(const float* __restrict__ X, const float* __restrict__ rw,
              const float* __restrict__ rb, int layer)
{
    int warp = (blockIdx.x * blockDim.x + threadIdx.x) >> 5;
    int lane = threadIdx.x & 31;
    if (warp >= NTOK) return;
    const float* x = X + (long)warp * DMODEL;
    float l[8] = {0, 0, 0, 0, 0, 0, 0, 0};
    for (int k = lane; k < DMODEL; k += 32) {
        float xv = x[k];
        const float* r = rw + k * 8;
        #pragma unroll
        for (int e = 0; e < 8; e++) l[e] = fmaf(xv, r[e], l[e]);
    }
    #pragma unroll
    for (int e = 0; e < 8; e++)
        #pragma unroll
        for (int o = 16; o; o >>= 1) l[e] += __shfl_down_sync(0xffffffffu, l[e], o);
    if (lane == 0) {
        float p[8]; float mx = -1e30f;
        #pragma unroll
        for (int e = 0; e < 8; e++) { p[e] = l[e] + rb[e]; mx = fmaxf(mx, p[e]); }
        float s = 0.f;
        #pragma unroll
        for (int e = 0; e < 8; e++) { p[e] = expf(p[e] - mx); s += p[e]; }
        float inv = 1.f / s;
        #pragma unroll
        for (int e = 0; e < 8; e++) p[e] *= inv;
        int i1 = 0;
        #pragma unroll
        for (int e = 1; e < 8; e++) if (p[e] > p[i1]) i1 = e;
        int i2 = -1;
        #pragma unroll
        for (int e = 0; e < 8; e++) {
            if (e == i1) continue;
            if (i2 < 0 || p[e] > p[i2]) i2 = e;
        }
        #pragma unroll
        for (int e = 0; e < 8; e++) atomicAdd(&g_imp[layer * 8 + e], p[e]);
        g_gates[2 * warp]     = p[i1];
        g_gates[2 * warp + 1] = p[i2];
        int q1 = atomicAdd(&g_counts[layer * 8 + i1], 1);
        g_lists[i1 * CAP + q1] = 2 * warp;
        int q2 = atomicAdd(&g_counts[layer * 8 + i2], 1);
        g_lists[i2 * CAP + q2] = 2 * warp + 1;
    }
}

__global__ void moe_combine_k(float* __restrict__ O)
{
    long i = (long)blockIdx.x * 256 + threadIdx.x;   // over NTOK*512
    long tok = i >> 9; int d = (int)(i & 511);
    O[i] = g_Y[(tok * 2) * DMODEL + d] + g_Y[(tok * 2 + 1) * DMODEL + d];
}

// ------------------------- pooling / loss ----------------------------------
__global__ void meanpool_k(const float* __restrict__ X, float* __restrict__ fv)
{
    int b = blockIdx.x, d = threadIdx.x;   // 512 threads
    float s = 0.f;
    for (int t = 0; t < 256; t++) s += X[((long)b * 256 + t) * DMODEL + d];
    fv[b * DMODEL + d] = s * (1.f / 256.f);
}

__global__ void loss_k(float* __restrict__ out)
{
    float L = 0.f;
    for (int layer = 0; layer < 2; layer++) {
        float s = 0.f;
        for (int e = 0; e < 8; e++)
            s += ((float)g_counts[layer * 8 + e] * (1.f / NTOK)) * (g_imp[layer * 8 + e] * (1.f / NTOK));
        L += 8.f * s;
    }
    out[0] = L;
}

// ------------------------- host --------------------------------------------
extern "C" void kernel_launch(void* const* d_in, const int* in_sizes, int n_in,
                              void* d_out, int out_size)
{
    const float* x     = (const float*)d_in[0];
    const float* pe_w  = (const float*)d_in[1];
    const float* pe_b  = (const float*)d_in[2];
    const float* pos   = (const float*)d_in[3];
    const float* ln1_g = (const float*)d_in[4];
    const float* ln1_b = (const float*)d_in[5];
    const float* ln2_g = (const float*)d_in[6];
    const float* ln2_b = (const float*)d_in[7];
    const float* ln3_g = (const float*)d_in[8];
    const float* ln3_b = (const float*)d_in[9];
    const float* wq = (const float*)d_in[10]; const float* bq = (const float*)d_in[11];
    const float* wk = (const float*)d_in[12]; const float* bk = (const float*)d_in[13];
    const float* wv = (const float*)d_in[14]; const float* bv = (const float*)d_in[15];
    const float* wo = (const float*)d_in[16]; const float* bo = (const float*)d_in[17];
    const float* m1_rw = (const float*)d_in[18]; const float* m1_rb = (const float*)d_in[19];
    const float* m1_w1 = (const float*)d_in[20]; const float* m1_b1 = (const float*)d_in[21];
    const float* m1_w2 = (const float*)d_in[22]; const float* m1_b2 = (const float*)d_in[23];
    const float* m2_rw = (const float*)d_in[24]; const float* m2_rb = (const float*)d_in[25];
    const float* m2_w1 = (const float*)d_in[26]; const float* m2_b1 = (const float*)d_in[27];
    const float* m2_w2 = (const float*)d_in[28]; const float* m2_b2 = (const float*)d_in[29];
    const float* cls_w = (const float*)d_in[30]; const float* cls_b = (const float*)d_in[31];
    float* out = (float*)d_out;

    void *p_patches, *p_e, *p_ln, *p_q, *p_k, *p_v, *p_ctx, *p_e2, *p_xm, *p_o1, *p_o2;
    cudaGetSymbolAddress(&p_patches, g_patches);
    cudaGetSymbolAddress(&p_e, g_e);
    cudaGetSymbolAddress(&p_ln, g_ln);
    cudaGetSymbolAddress(&p_q, g_q);
    cudaGetSymbolAddress(&p_k, g_k);
    cudaGetSymbolAddress(&p_v, g_v);
    cudaGetSymbolAddress(&p_ctx, g_ctx);
    cudaGetSymbolAddress(&p_e2, g_e2);
    cudaGetSymbolAddress(&p_xm, g_xm);
    cudaGetSymbolAddress(&p_o1, g_o1);
    cudaGetSymbolAddress(&p_o2, g_o2);
    void* p_attn; cudaGetSymbolAddress(&p_attn, g_attn);
    void *p_H, *p_Y;
    cudaGetSymbolAddress(&p_H, g_H);
    cudaGetSymbolAddress(&p_Y, g_Y);

    float* logits_out = out;            // [32,512]
    float* fv_out     = out + 16384;    // [32,512]
    float* loss_out   = out + 32768;    // [1]
    float* attnw_out  = out + 32769;    // [32,256,256]

    zero_k<<<1, 32>>>();

    // patch embed: e = patches @ pe_w + pe_b + pos   (K padded to 592)
    patchify_k<<<(NTOK * PDP + 255) / 256, 256>>>(x);
    gemm_f2<2><<<dim3(64, 4), 256>>>((const float*)p_patches, PDP, pe_w, DMODEL,
                                     (float*)p_e, DMODEL, NTOK, DMODEL, PDP,
                                     pe_b, pos, 0);

    // attention block
    layernorm_k<<<NTOK, 256>>>((const float*)p_e, ln1_g, ln1_b, (float*)p_ln);
    gemm_f2<0><<<dim3(64, 4), 256>>>((const float*)p_ln, DMODEL, wq, DMODEL,
                                     (float*)p_q, DMODEL, NTOK, DMODEL, DMODEL,
                                     bq, nullptr, 0);
    gemm_f2<0><<<dim3(64, 4), 256>>>((const float*)p_ln, DMODEL, wk, DMODEL,
                                     (float*)p_k, DMODEL, NTOK, DMODEL, DMODEL,
                                     bk, nullptr, 0);
    gemm_f2<0><<<dim3(64, 4), 256>>>((const float*)p_ln, DMODEL, wv, DMODEL,
                                     (float*)p_v, DMODEL, NTOK, DMODEL, DMODEL,
                                     bv, nullptr, 0);
    attn_scores_k<<<dim3(4, 4, 256), 256>>>((const float*)p_q, (const float*)p_k);
    softmax256_k<<<65536, 256>>>((float*)p_attn);
    attn_mean_k<<<NTOK, 256>>>(attnw_out);
    attn_ctx_k<<<dim3(4, 256), 256>>>((const float*)p_v);
    // e2 = ctx @ wo + bo + e
    gemm_f2<1><<<dim3(64, 4), 256>>>((const float*)p_ctx, DMODEL, wo, DMODEL,
                                     (float*)p_e2, DMODEL, NTOK, DMODEL, DMODEL,
                                     bo, (const float*)p_e, 0);

    // MoE layer 1
    layernorm_k<<<NTOK, 256>>>((const float*)p_e2, ln2_g, ln2_b, (float*)p_xm);
    router_k<<<NTOK * 32 / 256, 256>>>((const float*)p_xm, m1_rw, m1_rb, 0);
    gemm_f2<3><<<dim3(128, 16, 8), 256>>>((const float*)p_xm, DMODEL, m1_w1, HID,
                                          (float*)p_H, HID, CAP, HID, DMODEL,
                                          m1_b1, nullptr, 0);
    gemm_f2<4><<<dim3(128, 4, 8), 256>>>((const float*)p_H, HID, m1_w2, DMODEL,
                                         (float*)p_Y, DMODEL, CAP, DMODEL, HID,
                                         m1_b2, nullptr, 0);
    moe_combine_k<<<NTOK * DMODEL / 256, 256>>>((float*)p_o1);

    // MoE layer 2
    layernorm_k<<<NTOK, 256>>>((const float*)p_o1, ln3_g, ln3_b, (float*)p_xm);
    router_k<<<NTOK * 32 / 256, 256>>>((const float*)p_xm, m2_rw, m2_rb, 1);
    gemm_f2<3><<<dim3(128, 16, 8), 256>>>((const float*)p_xm, DMODEL, m2_w1, HID,
                                          (float*)p_H, HID, CAP, HID, DMODEL,
                                          m2_b1, nullptr, 1);
    gemm_f2<4><<<dim3(128, 4, 8), 256>>>((const float*)p_H, HID, m2_w2, DMODEL,
                                         (float*)p_Y, DMODEL, CAP, DMODEL, HID,
                                         m2_b2, nullptr, 1);
    moe_combine_k<<<NTOK * DMODEL / 256, 256>>>((float*)p_o2);

    // head
    meanpool_k<<<32, 512>>>((const float*)p_o2, fv_out);
    gemm_nn<0><<<dim3(1, 8), 256>>>(fv_out, DMODEL, cls_w, DMODEL,
                                    logits_out, DMODEL, 32, DMODEL, DMODEL,
                                    cls_b, nullptr);
    loss_k<<<1, 1>>>(loss_out);
}

// round 7
// speedup vs baseline: 1.1786x; 1.1786x over previous
#include <cuda_runtime.h>
#include <math.h>
#include <stdint.h>

#define NTOK 8192
#define DMODEL 512
#define HID 2048
#define CAP 16384
#define PD 588
#define PDP 608
#define STR 36
#define DSMEM2 (4 * 128 * STR * 4)   // 73728 bytes

__device__ float g_patches[(size_t)NTOK * PDP];
__device__ float g_e[(size_t)NTOK * DMODEL];
__device__ float g_ln[(size_t)NTOK * DMODEL];
__device__ float g_q[(size_t)NTOK * DMODEL];
__device__ float g_k[(size_t)NTOK * DMODEL];
__device__ float g_v[(size_t)NTOK * DMODEL];
__device__ float g_attn[(size_t)65536 * 256];
__device__ float g_ctx[(size_t)NTOK * DMODEL];
__device__ float g_e2[(size_t)NTOK * DMODEL];
__device__ float g_xm[(size_t)NTOK * DMODEL];
__device__ float g_H[(size_t)CAP * HID];
__device__ float g_Y[(size_t)CAP * DMODEL];
__device__ float g_o1[(size_t)NTOK * DMODEL];
__device__ float g_o2[(size_t)NTOK * DMODEL];
__device__ int g_lists[8 * CAP];
__device__ float g_gates[CAP];
__device__ int g_counts[16];
__device__ float g_imp[16];
__device__ float g_pewt[512 * PDP];
__device__ float g_wqt[512 * 512];
__device__ float g_wkt[512 * 512];
__device__ float g_wvt[512 * 512];
__device__ float g_wot[512 * 512];
__device__ float g_w1t[(size_t)8 * HID * DMODEL];
__device__ float g_w2t[(size_t)8 * DMODEL * HID];

__device__ __forceinline__ float gelu_f(float v) {
    return 0.5f * v * (1.0f + erff(v * 0.7071067811865476f));
}
// 3xTF32 split: hi exactly tf32-representable, lo rounded to tf32
__device__ __forceinline__ void split_tf32(float v, float& h, float& l) {
    h = __uint_as_float(__float_as_uint(v) & 0xFFFFE000u);
    float d = v - h;
    uint32_t lb;
    asm("cvt.rna.tf32.f32 %0, %1;" : "=r"(lb) : "f"(d));
    l = __uint_as_float(lb);
}
__device__ __forceinline__ void mma8(float* c, const uint32_t* a, const uint32_t* b) {
    asm volatile(
        "mma.sync.aligned.m16n8k8.row.col.f32.tf32.tf32.f32 "
        "{%0,%1,%2,%3}, {%4,%5,%6,%7}, {%8,%9}, {%0,%1,%2,%3};"
        : "+f"(c[0]), "+f"(c[1]), "+f"(c[2]), "+f"(c[3])
        : "r"(a[0]), "r"(a[1]), "r"(a[2]), "r"(a[3]), "r"(b[0]), "r"(b[1]));
}

__global__ void zero_k() {
    int t = threadIdx.x;
    if (t < 16) { g_counts[t] = 0; g_imp[t] = 0.f; }
}

__global__ void patchify_k(const float* __restrict__ x) {
    long t = (long)blockIdx.x * 256 + threadIdx.x;
    if (t >= (long)NTOK * PDP) return;
    int p = (int)(t % PDP);
    long token = t / PDP;
    if (p >= PD) { g_patches[t] = 0.f; return; }
    int b = (int)(token >> 8), s = (int)(token & 255);
    int hh = s >> 4, ww = s & 15;
    int c = p % 3, pp = p / 3;
    int p1 = pp / 14, p2 = pp % 14;
    g_patches[t] = x[(((long)b * 3 + c) * 224 + hh * 14 + p1) * 224 + ww * 14 + p2];
}

// in[R,C] (z-batched) -> out[C,Rpad], zero-pad rows >= R
__global__ __launch_bounds__(256)
void transpose_k(const float* __restrict__ in, float* __restrict__ out, int R, int Cc, int Rpad)
{
    __shared__ float t[32][33];
    int z = blockIdx.z;
    in  += (size_t)z * R * Cc;
    out += (size_t)z * Cc * Rpad;
    int r0 = blockIdx.x * 32, c0 = blockIdx.y * 32;
    int tx = threadIdx.x & 31, ty = threadIdx.x >> 5;
    #pragma unroll
    for (int i = 0; i < 4; i++) {
        int rr = r0 + ty + i * 8;
        t[ty + i * 8][tx] = (rr < R) ? in[(size_t)rr * Cc + c0 + tx] : 0.f;
    }
    __syncthreads();
    #pragma unroll
    for (int i = 0; i < 4; i++)
        out[(size_t)(c0 + ty + i * 8) * Rpad + r0 + tx] = t[tx][ty + i * 8];
}

// ------------- 3xTF32 mma.sync GEMM: C 128x128 tile = A @ Bt^T --------------
// Bt is [n_tot, K] row-major (K-major per n row).
// EPI 0 dense+bias | 1 +extra[m*512+n] | 2 +extra[(m&255)*512+n]
// EPI 3 gather(ent>>1), gelu | 4 gather(ent), *gate
template<int EPI>
__global__ __launch_bounds__(256, 1)
void gemm_mma(const float* __restrict__ A, int lda, const float* __restrict__ Bt,
              float* __restrict__ C, int ldc, int K, int n_tot,
              const float* __restrict__ bias, const float* __restrict__ extra, int layer)
{
    extern __shared__ float sm[];
    __shared__ int rows_s[128];
    float* sAh = sm;
    float* sAl = sm + 128 * STR;
    float* sBh = sm + 2 * 128 * STR;
    float* sBl = sm + 3 * 128 * STR;

    int tid = threadIdx.x, lane = tid & 31, w = tid >> 5;
    int m0 = blockIdx.x * 128, n0 = blockIdx.y * 128, e = blockIdx.z;

    if (EPI >= 3) {
        int cnt = g_counts[layer * 8 + e];
        if (m0 >= cnt) return;
        Bt += (size_t)e * n_tot * K;
        bias += (size_t)e * n_tot;
        if (tid < 128) rows_s[tid] = (m0 + tid < cnt) ? g_lists[e * CAP + m0 + tid] : -1;
        __syncthreads();
    }

    int r = tid >> 1, co = (tid & 1) * 16;
    const float* arow; bool aval = true;
    if (EPI == 3) { int ent = rows_s[r]; aval = (ent >= 0); arow = A + (size_t)(aval ? (ent >> 1) : 0) * lda; }
    else if (EPI == 4) { int ent = rows_s[r]; aval = (ent >= 0); arow = A + (size_t)(aval ? ent : 0) * lda; }
    else arow = A + (size_t)(m0 + r) * lda;
    const float* brow = Bt + (size_t)(n0 + r) * K;

    int wm = (w >> 2) * 64, wn = (w & 3) * 32;

    float acc[4][4][4];
    #pragma unroll
    for (int f = 0; f < 4; f++)
        #pragma unroll
        for (int g = 0; g < 4; g++)
            #pragma unroll
            for (int i = 0; i < 4; i++) acc[f][g][i] = 0.f;

    float4 av[4], bv[4];
    #pragma unroll
    for (int jj = 0; jj < 4; jj++) {
        av[jj] = aval ? *(const float4*)&arow[co + jj * 4] : make_float4(0.f, 0.f, 0.f, 0.f);
        bv[jj] = *(const float4*)&brow[co + jj * 4];
    }

    const uint32_t* uAh = (const uint32_t*)sAh;
    const uint32_t* uAl = (const uint32_t*)sAl;
    const uint32_t* uBh = (const uint32_t*)sBh;
    const uint32_t* uBl = (const uint32_t*)sBl;

    int NC = K / 32;
    for (int c = 0; c < NC; c++) {
        __syncthreads();   // previous chunk's compute done
        #pragma unroll
        for (int jj = 0; jj < 4; jj++) {
            float4 ah, al, bh, bl;
            split_tf32(av[jj].x, ah.x, al.x); split_tf32(av[jj].y, ah.y, al.y);
            split_tf32(av[jj].z, ah.z, al.z); split_tf32(av[jj].w, ah.w, al.w);
            split_tf32(bv[jj].x, bh.x, bl.x); split_tf32(bv[jj].y, bh.y, bl.y);
            split_tf32(bv[jj].z, bh.z, bl.z); split_tf32(bv[jj].w, bh.w, bl.w);
            *(float4*)&sAh[r * STR + co + 4 * jj] = ah;
            *(float4*)&sAl[r * STR + co + 4 * jj] = al;
            *(float4*)&sBh[r * STR + co + 4 * jj] = bh;
            *(float4*)&sBl[r * STR + co + 4 * jj] = bl;
        }
        __syncthreads();
        if (c + 1 < NC) {
            #pragma unroll
            for (int jj = 0; jj < 4; jj++) {
                av[jj] = aval ? *(const float4*)&arow[(c + 1) * 32 + co + jj * 4]
                              : make_float4(0.f, 0.f, 0.f, 0.f);
                bv[jj] = *(const float4*)&brow[(c + 1) * 32 + co + jj * 4];
            }
        }
        #pragma unroll
        for (int s = 0; s < 4; s++) {
            int k0 = s * 8;
            uint32_t ahf[4][4], alf[4][4], bhf[4][2], blf[4][2];
            #pragma unroll
            for (int f = 0; f < 4; f++) {
                int ar = wm + 16 * f + (lane >> 2);
                int ac = k0 + (lane & 3);
                ahf[f][0] = uAh[ar * STR + ac];
                ahf[f][1] = uAh[(ar + 8) * STR + ac];
                ahf[f][2] = uAh[ar * STR + ac + 4];
                ahf[f][3] = uAh[(ar + 8) * STR + ac + 4];
                alf[f][0] = uAl[ar * STR + ac];
                alf[f][1] = uAl[(ar + 8) * STR + ac];
                alf[f][2] = uAl[ar * STR + ac + 4];
                alf[f][3] = uAl[(ar + 8) * STR + ac + 4];
            }
            #pragma unroll
            for (int g = 0; g < 4; g++) {
                int br_ = wn + 8 * g + (lane >> 2);
                int bc = k0 + (lane & 3);
                bhf[g][0] = uBh[br_ * STR + bc];
                bhf[g][1] = uBh[br_ * STR + bc + 4];
                blf[g][0] = uBl[br_ * STR + bc];
                blf[g][1] = uBl[br_ * STR + bc + 4];
            }
            #pragma unroll
            for (int f = 0; f < 4; f++)
                #pragma unroll
                for (int g = 0; g < 4; g++) {
                    mma8(acc[f][g], ahf[f], bhf[g]);
                    mma8(acc[f][g], ahf[f], blf[g]);
                    mma8(acc[f][g], alf[f], bhf[g]);
                }
        }
    }

    // epilogue straight from fragments
    #pragma unroll
    for (int f = 0; f < 4; f++) {
        int row0 = wm + 16 * f + (lane >> 2);
        #pragma unroll
        for (int g = 0; g < 4; g++) {
            int ncol = wn + 8 * g + 2 * (lane & 3);
            int n = n0 + ncol;
            #pragma unroll
            for (int hh = 0; hh < 2; hh++) {
                int mloc = row0 + hh * 8;
                float v0 = acc[f][g][hh * 2] + bias[n];
                float v1 = acc[f][g][hh * 2 + 1] + bias[n + 1];
                if (EPI <= 2) {
                    size_t m = (size_t)(m0 + mloc);
                    if (EPI == 1) {
                        const float* ex = extra + m * 512 + n;
                        v0 += ex[0]; v1 += ex[1];
                    }
                    if (EPI == 2) {
                        const float* ex = extra + (size_t)((m0 + mloc) & 255) * 512 + n;
                        v0 += ex[0]; v1 += ex[1];
                    }
                    *(float2*)&C[m * ldc + n] = make_float2(v0, v1);
                } else {
                    int ent = rows_s[mloc];
                    if (ent >= 0) {
                        if (EPI == 3) { v0 = gelu_f(v0); v1 = gelu_f(v1); }
                        else { float gt = g_gates[ent]; v0 *= gt; v1 *= gt; }
                        *(float2*)&C[(size_t)ent * ldc + n] = make_float2(v0, v1);
                    }
                }
            }
        }
    }
}

// ---------------- small SIMT GEMM (cls head) --------------------------------
__global__ __launch_bounds__(256)
void gemm_nn(const float* __restrict__ A, const float* __restrict__ B,
             float* __restrict__ C, int M, int N, int K, const float* __restrict__ bias)
{
    __shared__ float As[16][65], Bs[16][65];
    int tid = threadIdx.x, tx = tid & 15, ty = tid >> 4;
    int m0 = blockIdx.x * 64, n0 = blockIdx.y * 64;
    float acc[4][4] = {};
    for (int kk = 0; kk < K; kk += 16) {
        #pragma unroll
        for (int i = 0; i < 4; i++) {
            int idx = tid + i * 256, rr = idx >> 4, cc = idx & 15;
            As[cc][rr] = (m0 + rr < M) ? A[(long)(m0 + rr) * K + kk + cc] : 0.f;
        }
        #pragma unroll
        for (int i = 0; i < 4; i++) {
            int idx = tid + i * 256, rr = idx >> 6, cc = idx & 63;
            Bs[rr][cc] = B[(long)(kk + rr) * N + n0 + cc];
        }
        __syncthreads();
        #pragma unroll
        for (int k = 0; k < 16; k++) {
            float a[4], b[4];
            #pragma unroll
            for (int i = 0; i < 4; i++) a[i] = As[k][ty * 4 + i];
            #pragma unroll
            for (int j = 0; j < 4; j++) b[j] = Bs[k][tx * 4 + j];
            #pragma unroll
            for (int i = 0; i < 4; i++)
                #pragma unroll
                for (int j = 0; j < 4; j++) acc[i][j] = fmaf(a[i], b[j], acc[i][j]);
        }
        __syncthreads();
    }
    #pragma unroll
    for (int i = 0; i < 4; i++) {
        int m = m0 + ty * 4 + i;
        if (m >= M) continue;
        #pragma unroll
        for (int j = 0; j < 4; j++) {
            int n = n0 + tx * 4 + j;
            C[(long)m * N + n] = acc[i][j] + bias[n];
        }
    }
}

__global__ __launch_bounds__(256)
void layernorm_k(const float* __restrict__ X, const float* __restrict__ g,
                 const float* __restrict__ bb, float* __restrict__ Y)
{
    __shared__ float red[8];
    __shared__ float mean_s, inv_s;
    long row = blockIdx.x;
    const float* x = X + row * DMODEL;
    int t = threadIdx.x;
    float v0 = x[t], v1 = x[t + 256];
    float s = v0 + v1;
    #pragma unroll
    for (int o = 16; o; o >>= 1) s += __shfl_down_sync(0xffffffffu, s, o);
    if ((t & 31) == 0) red[t >> 5] = s;
    __syncthreads();
    if (t == 0) {
        float q = 0.f;
        #pragma unroll
        for (int w = 0; w < 8; w++) q += red[w];
        mean_s = q * (1.f / DMODEL);
    }
    __syncthreads();
    float mean = mean_s;
    float d0 = v0 - mean, d1 = v1 - mean;
    float s2 = d0 * d0 + d1 * d1;
    #pragma unroll
    for (int o = 16; o; o >>= 1) s2 += __shfl_down_sync(0xffffffffu, s2, o);
    if ((t & 31) == 0) red[t >> 5] = s2;
    __syncthreads();
    if (t == 0) {
        float q = 0.f;
        #pragma unroll
        for (int w = 0; w < 8; w++) q += red[w];
        inv_s = rsqrtf(q * (1.f / DMODEL) + 1e-5f);
    }
    __syncthreads();
    float inv = inv_s;
    Y[row * DMODEL + t] = d0 * inv * g[t] + bb[t];
    Y[row * DMODEL + t + 256] = d1 * inv * g[t + 256] + bb[t + 256];
}

__global__ __launch_bounds__(256)
void attn_scores_k(const float* __restrict__ Q, const float* __restrict__ Kt)
{
    int bh = blockIdx.z, b = bh >> 3, h = bh & 7;
    const float* A = Q + (long)b * 256 * 512 + h * 64;
    const float* B = Kt + (long)b * 256 * 512 + h * 64;
    float* C = g_attn + (long)bh * 65536;
    int m0 = blockIdx.x * 64, n0 = blockIdx.y * 64;
    __shared__ float As[16][65], Bs[16][65];
    int tid = threadIdx.x, tx = tid & 15, ty = tid >> 4;
    float acc[4][4] = {};
    for (int kk = 0; kk < 64; kk += 16) {
        #pragma unroll
        for (int i = 0; i < 4; i++) {
            int idx = tid + i * 256, rr = idx >> 4, cc = idx & 15;
            As[cc][rr] = A[(long)(m0 + rr) * 512 + kk + cc];
            Bs[cc][rr] = B[(long)(n0 + rr) * 512 + kk + cc];
        }
        __syncthreads();
        #pragma unroll
        for (int k = 0; k < 16; k++) {
            float a[4], bv[4];
            #pragma unroll
            for (int i = 0; i < 4; i++) a[i] = As[k][ty * 4 + i];
            #pragma unroll
            for (int j = 0; j < 4; j++) bv[j] = Bs[k][tx * 4 + j];
            #pragma unroll
            for (int i = 0; i < 4; i++)
                #pragma unroll
                for (int j = 0; j < 4; j++) acc[i][j] = fmaf(a[i], bv[j], acc[i][j]);
        }
        __syncthreads();
    }
    #pragma unroll
    for (int i = 0; i < 4; i++)
        #pragma unroll
        for (int j = 0; j < 4; j++)
            C[(long)(m0 + ty * 4 + i) * 256 + n0 + tx * 4 + j] = acc[i][j] * 0.125f;
}

__global__ __launch_bounds__(256)
void softmax256_k(float* __restrict__ S)
{
    __shared__ float red[8];
    __shared__ float mx_s, sum_s;
    long row = blockIdx.x;
    float* p = S + row * 256;
    int t = threadIdx.x;
    float v = p[t], m = v;
    #pragma unroll
    for (int o = 16; o; o >>= 1) m = fmaxf(m, __shfl_xor_sync(0xffffffffu, m, o));
    if ((t & 31) == 0) red[t >> 5] = m;
    __syncthreads();
    if (t == 0) {
        float q = red[0];
        #pragma unroll
        for (int w = 1; w < 8; w++) q = fmaxf(q, red[w]);
        mx_s = q;
    }
    __syncthreads();
    float ex = expf(v - mx_s), s = ex;
    #pragma unroll
    for (int o = 16; o; o >>= 1) s += __shfl_xor_sync(0xffffffffu, s, o);
    if ((t & 31) == 0) red[t >> 5] = s;
    __syncthreads();
    if (t == 0) {
        float q = 0.f;
        #pragma unroll
        for (int w = 0; w < 8; w++) q += red[w];
        sum_s = q;
    }
    __syncthreads();
    p[t] = ex / sum_s;
}

__global__ __launch_bounds__(256)
void attn_ctx_k(const float* __restrict__ V)
{
    int bh = blockIdx.y, b = bh >> 3, h = bh & 7;
    const float* A = g_attn + (long)bh * 65536;
    int m0 = blockIdx.x * 64;
    __shared__ float As[16][65], Bs[16][65];
    int tid = threadIdx.x, tx = tid & 15, ty = tid >> 4;
    float acc[4][4] = {};
    for (int kk = 0; kk < 256; kk += 16) {
        #pragma unroll
        for (int i = 0; i < 4; i++) {
            int idx = tid + i * 256, rr = idx >> 4, cc = idx & 15;
            As[cc][rr] = A[(long)(m0 + rr) * 256 + kk + cc];
        }
        #pragma unroll
        for (int i = 0; i < 4; i++) {
            int idx = tid + i * 256, rr = idx >> 6, cc = idx & 63;
            Bs[rr][cc] = V[((long)b * 256 + kk + rr) * 512 + h * 64 + cc];
        }
        __syncthreads();
        #pragma unroll
        for (int k = 0; k < 16; k++) {
            float a[4], bv[4];
            #pragma unroll
            for (int i = 0; i < 4; i++) a[i] = As[k][ty * 4 + i];
            #pragma unroll
            for (int j = 0; j < 4; j++) bv[j] = Bs[k][tx * 4 + j];
            #pragma unroll
            for (int i = 0; i < 4; i++)
                #pragma unroll
                for (int j = 0; j < 4; j++) acc[i][j] = fmaf(a[i], bv[j], acc[i][j]);
        }
        __syncthreads();
    }
    #pragma unroll
    for (int i = 0; i < 4; i++)
        #pragma unroll
        for (int j = 0; j < 4; j++)
            g_ctx[((long)b * 256 + m0 + ty * 4 + i) * 512 + h * 64 + tx * 4 + j] = acc[i][j];
}

__global__ __launch_bounds__(256)
void attn_mean_k(float* __restrict__ out)
{
    __shared__ float red[8];
    __shared__ float mx_s, sum_s;
    int row = blockIdx.x, b = row >> 8, q = row & 255;
    int t = threadIdx.x;
    float s = 0.f;
    #pragma unroll
    for (int h = 0; h < 8; h++) s += g_attn[(((long)(b * 8 + h)) * 256 + q) * 256 + t];
    s *= 0.125f;
    float m = s;
    #pragma unroll
    for (int o = 16; o; o >>= 1) m = fmaxf(m, __shfl_xor_sync(0xffffffffu, m, o));
    if ((t & 31) == 0) red[t >> 5] = m;
    __syncthreads();
    if (t == 0) {
        float q2 = red[0];
        #pragma unroll
        for (int w = 1; w < 8; w++) q2 = fmaxf(q2, red[w]);
        mx_s = q2;
    }
    __syncthreads();
    float ex = expf(s - mx_s), ss = ex;
    #pragma unroll
    for (int o = 16; o; o >>= 1) ss += __shfl_xor_sync(0xffffffffu, ss, o);
    if ((t & 31) == 0) red[t >> 5] = ss;
    __syncthreads();
    if (t == 0) {
        float q2 = 0.f;
        #pragma unroll
        for (int w = 0; w < 8; w++) q2 += red[w];
        sum_s = q2;
    }
    __syncthreads();
    out[(long)row * 256 + t] = ex / sum_s;
}

__global__ __launch_bounds__(256)
void router_k(const float* __restrict__ X, const float* __restrict__ rw,
              const float* __restrict__ rb, int layer)
{
    int warp = (blockIdx.x * blockDim.x + threadIdx.x) >> 5;
    int lane = threadIdx.x & 31;
    if (warp >= NTOK) return;
    const float* x = X + (long)warp * DMODEL;
    float l[8] = {0,0,0,0,0,0,0,0};
    for (int k = lane; k < DMODEL; k += 32) {
        float xv = x[k];
        const float* rr = rw + k * 8;
        #pragma unroll
        for (int e = 0; e < 8; e++) l[e] = fmaf(xv, rr[e], l[e]);
    }
    #pragma unroll
    for (int e = 0; e < 8; e++)
        #pragma unroll
        for (int o = 16; o; o >>= 1) l[e] += __shfl_down_sync(0xffffffffu, l[e], o);
    if (lane == 0) {
        float p[8], mx = -1e30f;
        #pragma unroll
        for (int e = 0; e < 8; e++) { p[e] = l[e] + rb[e]; mx = fmaxf(mx, p[e]); }
        float s = 0.f;
        #pragma unroll
        for (int e = 0; e < 8; e++) { p[e] = expf(p[e] - mx); s += p[e]; }
        float inv = 1.f / s;
        #pragma unroll
        for (int e = 0; e < 8; e++) p[e] *= inv;
        int i1 = 0;
        #pragma unroll
        for (int e = 1; e < 8; e++) if (p[e] > p[i1]) i1 = e;
        int i2 = -1;
        #pragma unroll
        for (int e = 0; e < 8; e++) {
            if (e == i1) continue;
            if (i2 < 0 || p[e] > p[i2]) i2 = e;
        }
        #pragma unroll
        for (int e = 0; e < 8; e++) atomicAdd(&g_imp[layer * 8 + e], p[e]);
        g_gates[2 * warp] = p[i1];
        g_gates[2 * warp + 1] = p[i2];
        int q1 = atomicAdd(&g_counts[layer * 8 + i1], 1);
        g_lists[i1 * CAP + q1] = 2 * warp;
        int q2 = atomicAdd(&g_counts[layer * 8 + i2], 1);
        g_lists[i2 * CAP + q2] = 2 * warp + 1;
    }
}

__global__ void moe_combine_k(float* __restrict__ O)
{
    long i = (long)blockIdx.x * 256 + threadIdx.x;
    long tok = i >> 9; int d = (int)(i & 511);
    O[i] = g_Y[(tok * 2) * DMODEL + d] + g_Y[(tok * 2 + 1) * DMODEL + d];
}

__global__ void meanpool_k(const float* __restrict__ X, float* __restrict__ fv)
{
    int b = blockIdx.x, d = threadIdx.x;
    float s = 0.f;
    for (int t = 0; t < 256; t++) s += X[((long)b * 256 + t) * DMODEL + d];
    fv[b * DMODEL + d] = s * (1.f / 256.f);
}

__global__ void loss_k(float* __restrict__ out)
{
    float L = 0.f;
    for (int layer = 0; layer < 2; layer++) {
        float s = 0.f;
        for (int e = 0; e < 8; e++)
            s += ((float)g_counts[layer * 8 + e] * (1.f / NTOK)) * (g_imp[layer * 8 + e] * (1.f / NTOK));
        L += 8.f * s;
    }
    out[0] = L;
}

extern "C" void kernel_launch(void* const* d_in, const int* in_sizes, int n_in,
                              void* d_out, int out_size)
{
    const float* x = (const float*)d_in[0];
    const float* pe_w = (const float*)d_in[1];
    const float* pe_b = (const float*)d_in[2];
    const float* pos = (const float*)d_in[3];
    const float* ln1_g = (const float*)d_in[4]; const float* ln1_b = (const float*)d_in[5];
    const float* ln2_g = (const float*)d_in[6]; const float* ln2_b = (const float*)d_in[7];
    const float* ln3_g = (const float*)d_in[8]; const float* ln3_b = (const float*)d_in[9];
    const float* wq = (const float*)d_in[10]; const float* bq = (const float*)d_in[11];
    const float* wk = (const float*)d_in[12]; const float* bk = (const float*)d_in[13];
    const float* wv = (const float*)d_in[14]; const float* bv = (const float*)d_in[15];
    const float* wo = (const float*)d_in[16]; const float* bo = (const float*)d_in[17];
    const float* m1_rw = (const float*)d_in[18]; const float* m1_rb = (const float*)d_in[19];
    const float* m1_w1 = (const float*)d_in[20]; const float* m1_b1 = (const float*)d_in[21];
    const float* m1_w2 = (const float*)d_in[22]; const float* m1_b2 = (const float*)d_in[23];
    const float* m2_rw = (const float*)d_in[24]; const float* m2_rb = (const float*)d_in[25];
    const float* m2_w1 = (const float*)d_in[26]; const float* m2_b1 = (const float*)d_in[27];
    const float* m2_w2 = (const float*)d_in[28]; const float* m2_b2 = (const float*)d_in[29];
    const float* cls_w = (const float*)d_in[30]; const float* cls_b = (const float*)d_in[31];
    float* out = (float*)d_out;

    cudaFuncSetAttribute(gemm_mma<0>, cudaFuncAttributeMaxDynamicSharedMemorySize, DSMEM2);
    cudaFuncSetAttribute(gemm_mma<1>, cudaFuncAttributeMaxDynamicSharedMemorySize, DSMEM2);
    cudaFuncSetAttribute(gemm_mma<2>, cudaFuncAttributeMaxDynamicSharedMemorySize, DSMEM2);
    cudaFuncSetAttribute(gemm_mma<3>, cudaFuncAttributeMaxDynamicSharedMemorySize, DSMEM2);
    cudaFuncSetAttribute(gemm_mma<4>, cudaFuncAttributeMaxDynamicSharedMemorySize, DSMEM2);

    void *pP, *pE, *pL, *pQ, *pK, *pV, *pC, *pE2, *pX, *pO1, *pO2, *pA, *pH, *pY;
    void *tPE, *tQ, *tK, *tV, *tO, *tW1, *tW2;
    cudaGetSymbolAddress(&pP, g_patches); cudaGetSymbolAddress(&pE, g_e);
    cudaGetSymbolAddress(&pL, g_ln); cudaGetSymbolAddress(&pQ, g_q);
    cudaGetSymbolAddress(&pK, g_k); cudaGetSymbolAddress(&pV, g_v);
    cudaGetSymbolAddress(&pC, g_ctx); cudaGetSymbolAddress(&pE2, g_e2);
    cudaGetSymbolAddress(&pX, g_xm); cudaGetSymbolAddress(&pO1, g_o1);
    cudaGetSymbolAddress(&pO2, g_o2); cudaGetSymbolAddress(&pA, g_attn);
    cudaGetSymbolAddress(&pH, g_H); cudaGetSymbolAddress(&pY, g_Y);
    cudaGetSymbolAddress(&tPE, g_pewt); cudaGetSymbolAddress(&tQ, g_wqt);
    cudaGetSymbolAddress(&tK, g_wkt); cudaGetSymbolAddress(&tV, g_wvt);
    cudaGetSymbolAddress(&tO, g_wot); cudaGetSymbolAddress(&tW1, g_w1t);
    cudaGetSymbolAddress(&tW2, g_w2t);

    float* logits_out = out;
    float* fv_out = out + 16384;
    float* loss_out = out + 32768;
    float* attnw_out = out + 32769;

    zero_k<<<1, 32>>>();
    patchify_k<<<(NTOK * PDP + 255) / 256, 256>>>(x);
    transpose_k<<<dim3(19, 16), 256>>>(pe_w, (float*)tPE, PD, 512, PDP);
    transpose_k<<<dim3(16, 16), 256>>>(wq, (float*)tQ, 512, 512, 512);
    transpose_k<<<dim3(16, 16), 256>>>(wk, (float*)tK, 512, 512, 512);
    transpose_k<<<dim3(16, 16), 256>>>(wv, (float*)tV, 512, 512, 512);
    transpose_k<<<dim3(16, 16), 256>>>(wo, (float*)tO, 512, 512, 512);

    gemm_mma<2><<<dim3(64, 4), 256, DSMEM2>>>((const float*)pP, PDP, (const float*)tPE,
                                              (float*)pE, 512, PDP, 512, pe_b, pos, 0);
    layernorm_k<<<NTOK, 256>>>((const float*)pE, ln1_g, ln1_b, (float*)pL);
    gemm_mma<0><<<dim3(64, 4), 256, DSMEM2>>>((const float*)pL, 512, (const float*)tQ,
                                              (float*)pQ, 512, 512, 512, bq, nullptr, 0);
    gemm_mma<0><<<dim3(64, 4), 256, DSMEM2>>>((const float*)pL, 512, (const float*)tK,
                                              (float*)pK, 512, 512, 512, bk, nullptr, 0);
    gemm_mma<0><<<dim3(64, 4), 256, DSMEM2>>>((const float*)pL, 512, (const float*)tV,
                                              (float*)pV, 512, 512, 512, bv, nullptr, 0);
    attn_scores_k<<<dim3(4, 4, 256), 256>>>((const float*)pQ, (const float*)pK);
    softmax256_k<<<65536, 256>>>((float*)pA);
    attn_mean_k<<<NTOK, 256>>>(attnw_out);
    attn_ctx_k<<<dim3(4, 256), 256>>>((const float*)pV);
    gemm_mma<1><<<dim3(64, 4), 256, DSMEM2>>>((const float*)pC, 512, (const float*)tO,
                                              (float*)pE2, 512, 512, 512, bo, (const float*)pE, 0);

    // MoE layer 1
    layernorm_k<<<NTOK, 256>>>((const float*)pE2, ln2_g, ln2_b, (float*)pX);
    router_k<<<NTOK / 8, 256>>>((const float*)pX, m1_rw, m1_rb, 0);
    transpose_k<<<dim3(16, 64, 8), 256>>>(m1_w1, (float*)tW1, 512, 2048, 512);
    transpose_k<<<dim3(64, 16, 8), 256>>>(m1_w2, (float*)tW2, 2048, 512, 2048);
    gemm_mma<3><<<dim3(128, 16, 8), 256, DSMEM2>>>((const float*)pX, 512, (const float*)tW1,
                                                   (float*)pH, 2048, 512, 2048, m1_b1, nullptr, 0);
    gemm_mma<4><<<dim3(128, 4, 8), 256, DSMEM2>>>((const float*)pH, 2048, (const float*)tW2,
                                                  (float*)pY, 512, 2048, 512, m1_b2, nullptr, 0);
    moe_combine_k<<<NTOK * DMODEL / 256, 256>>>((float*)pO1);

    // MoE layer 2
    layernorm_k<<<NTOK, 256>>>((const float*)pO1, ln3_g, ln3_b, (float*)pX);
    router_k<<<NTOK / 8, 256>>>((const float*)pX, m2_rw, m2_rb, 1);
    transpose_k<<<dim3(16, 64, 8), 256>>>(m2_w1, (float*)tW1, 512, 2048, 512);
    transpose_k<<<dim3(64, 16, 8), 256>>>(m2_w2, (float*)tW2, 2048, 512, 2048);
    gemm_mma<3><<<dim3(128, 16, 8), 256, DSMEM2>>>((const float*)pX, 512, (const float*)tW1,
                                                   (float*)pH, 2048, 512, 2048, m2_b1, nullptr, 1);
    gemm_mma<4><<<dim3(128, 4, 8), 256, DSMEM2>>>((const float*)pH, 2048, (const float*)tW2,
                                                  (float*)pY, 512, 2048, 512, m2_b2, nullptr, 1);
    moe_combine_k<<<NTOK * DMODEL / 256, 256>>>((float*)pO2);

    meanpool_k<<<32, 512>>>((const float*)pO2, fv_out);
    gemm_nn<<<dim3(1, 8), 256>>>(fv_out, cls_w, logits_out, 32, 512, 512, cls_b);
    loss_k<<<1, 1>>>(loss_out);
}